// round 2
// baseline (speedup 1.0000x reference)
#include <cuda_runtime.h>
#include <math.h>

#define SS 4096
#define CC 2048
#define HH 16
#define DD 128
#define EPSF 1.1920929e-07f

// Scratch (no cudaMalloc allowed): Q, K, V after projection, attention output.
__device__ float g_q[SS * CC];
__device__ float g_k[SS * CC];
__device__ float g_v[SS * CC];
__device__ float g_attn[SS * CC];

// ---------------------------------------------------------------------------
// GEMM: Out[M,N] = A[M,K] @ B[N,K]^T + bias[N]
// Both A and B are K-contiguous (row-major with K as fastest dim) -> "NT" GEMM.
// Block tile 128x64, K-tile 16, 256 threads, 8x4 per thread.
// ---------------------------------------------------------------------------
__global__ void gemm_nt_bias(const float* __restrict__ A,
                             const float* __restrict__ B,
                             const float* __restrict__ bias,
                             float* __restrict__ Out,
                             int M, int N, int K)
{
    const int BM = 128, BN = 64, BK = 16;
    __shared__ float As[BK][BM + 1];
    __shared__ float Bs[BK][BN + 1];

    const int t  = threadIdx.x;
    const int tx = t & 15;        // 0..15 -> cols
    const int ty = t >> 4;        // 0..15 -> rows
    const int m0 = blockIdx.y * BM;
    const int n0 = blockIdx.x * BN;

    float acc[8][4];
#pragma unroll
    for (int i = 0; i < 8; i++)
#pragma unroll
        for (int j = 0; j < 4; j++) acc[i][j] = 0.0f;

    for (int k0 = 0; k0 < K; k0 += BK) {
        // Load A tile: 128x16 = 2048 floats, 8 per thread, coalesced on K.
#pragma unroll
        for (int i = 0; i < 8; i++) {
            int idx = i * 256 + t;
            int m = idx >> 4, kk = idx & 15;
            As[kk][m] = A[(size_t)(m0 + m) * K + k0 + kk];
        }
        // Load B tile: 64x16 = 1024 floats, 4 per thread.
#pragma unroll
        for (int i = 0; i < 4; i++) {
            int idx = i * 256 + t;
            int n = idx >> 4, kk = idx & 15;
            Bs[kk][n] = B[(size_t)(n0 + n) * K + k0 + kk];
        }
        __syncthreads();

#pragma unroll
        for (int kk = 0; kk < BK; kk++) {
            float a[8], b[4];
#pragma unroll
            for (int i = 0; i < 8; i++) a[i] = As[kk][ty * 8 + i];
#pragma unroll
            for (int j = 0; j < 4; j++) b[j] = Bs[kk][tx * 4 + j];
#pragma unroll
            for (int i = 0; i < 8; i++)
#pragma unroll
                for (int j = 0; j < 4; j++)
                    acc[i][j] = fmaf(a[i], b[j], acc[i][j]);
        }
        __syncthreads();
    }

#pragma unroll
    for (int i = 0; i < 8; i++) {
        int m = m0 + ty * 8 + i;
#pragma unroll
        for (int j = 0; j < 4; j++) {
            int n = n0 + tx * 4 + j;
            Out[(size_t)m * N + n] = acc[i][j] + bias[n];
        }
    }
}

// ---------------------------------------------------------------------------
// Fused per-head RMSNorm (over D=128) + table-driven rotary.
// grid.x = S*H (one (s,h) per block), grid.y = 0 -> q, 1 -> k. 128 threads.
// ---------------------------------------------------------------------------
__global__ void norm_rope(float* __restrict__ q, float* __restrict__ k,
                          const float* __restrict__ qw,
                          const float* __restrict__ kw,
                          const float* __restrict__ rope)
{
    const int sh = blockIdx.x;          // s*H + h
    const int s  = sh >> 4;             // /H
    float* x       = (blockIdx.y == 0) ? q  : k;
    const float* w = (blockIdx.y == 0) ? qw : kw;

    const int d = threadIdx.x;
    float v = x[(size_t)sh * DD + d];

    // block-reduce sum of squares (128 threads = 4 warps)
    float ss = v * v;
#pragma unroll
    for (int o = 16; o > 0; o >>= 1) ss += __shfl_xor_sync(0xffffffffu, ss, o);
    __shared__ float wsum[4];
    __shared__ float nrm[DD];
    if ((d & 31) == 0) wsum[d >> 5] = ss;
    __syncthreads();
    float tot = wsum[0] + wsum[1] + wsum[2] + wsum[3];
    float inv = rsqrtf(tot * (1.0f / DD) + EPSF);
    nrm[d] = v * inv * w[d];
    __syncthreads();

    // rotary: rope[s,0,p,i,j] at s*256 + p*4 + i*2 + j ; d = 2p + i
    int p = d >> 1, i = d & 1;
    const float* r = rope + (size_t)s * 256 + p * 4 + i * 2;
    float out = r[0] * nrm[2 * p] + r[1] * nrm[2 * p + 1];
    x[(size_t)sh * DD + d] = out;
}

// ---------------------------------------------------------------------------
// Flash attention, fp32, online softmax.
// Block: (head, 64-query tile). 256 threads as 16x16; each thread owns
// 4 query rows x (4 score cols / 8 strided O cols). BK = 64.
// Dynamic smem: Qs 64x128 + Ks 64x128 + Vs 64x128 + Ps 64x64 = 112 KB.
// ---------------------------------------------------------------------------
__global__ void flash_attn(const float* __restrict__ q,
                           const float* __restrict__ k,
                           const float* __restrict__ v,
                           float* __restrict__ o)
{
    const int BQ = 64, BK = 64;
    extern __shared__ float sm[];
    float* Qs = sm;                    // [64][128]
    float* Ks = Qs + BQ * DD;          // [64][128]
    float* Vs = Ks + BK * DD;          // [64][128]
    float* Ps = Vs + BK * DD;          // [64][64]

    const int h  = blockIdx.y;
    const int q0 = blockIdx.x * BQ;
    const int t  = threadIdx.x;
    const int tx = t & 15, ty = t >> 4;
    const float scale = 0.08838834764831845f;   // 1/sqrt(128)

    // Load Q tile (coalesced: consecutive threads -> consecutive d)
#pragma unroll
    for (int i = 0; i < 32; i++) {
        int idx = i * 256 + t;              // 0..8191
        int r = idx >> 7, c = idx & 127;
        Qs[idx] = q[((size_t)(q0 + r) * HH + h) * DD + c];
    }

    float m_i[4], l_i[4], oacc[4][8];
#pragma unroll
    for (int i = 0; i < 4; i++) {
        m_i[i] = -1e30f;
        l_i[i] = 0.0f;
#pragma unroll
        for (int c = 0; c < 8; c++) oacc[i][c] = 0.0f;
    }

    for (int k0 = 0; k0 < SS; k0 += BK) {
        __syncthreads();    // prev-iter Ps/Vs reads done before overwrite
#pragma unroll
        for (int i = 0; i < 32; i++) {
            int idx = i * 256 + t;
            int r = idx >> 7, c = idx & 127;
            Ks[idx] = k[((size_t)(k0 + r) * HH + h) * DD + c];
            Vs[idx] = v[((size_t)(k0 + r) * HH + h) * DD + c];
        }
        __syncthreads();

        // scores: 64x64 = Q . K^T
        float acc[4][4];
#pragma unroll
        for (int i = 0; i < 4; i++)
#pragma unroll
            for (int j = 0; j < 4; j++) acc[i][j] = 0.0f;

#pragma unroll 4
        for (int kk = 0; kk < DD; kk++) {
            float a[4], b[4];
#pragma unroll
            for (int i = 0; i < 4; i++) a[i] = Qs[(ty * 4 + i) * DD + kk];
#pragma unroll
            for (int j = 0; j < 4; j++) b[j] = Ks[(tx * 4 + j) * DD + kk];
#pragma unroll
            for (int i = 0; i < 4; i++)
#pragma unroll
                for (int j = 0; j < 4; j++)
                    acc[i][j] = fmaf(a[i], b[j], acc[i][j]);
        }

        // online softmax per query row (16 tx threads share a row)
#pragma unroll
        for (int i = 0; i < 4; i++) {
            float rmax = fmaxf(fmaxf(acc[i][0], acc[i][1]),
                               fmaxf(acc[i][2], acc[i][3])) * scale;
#pragma unroll
            for (int o2 = 1; o2 < 16; o2 <<= 1)
                rmax = fmaxf(rmax, __shfl_xor_sync(0xffffffffu, rmax, o2));
            float mnew = fmaxf(m_i[i], rmax);
            float corr = __expf(m_i[i] - mnew);
            float psum = 0.0f;
#pragma unroll
            for (int j = 0; j < 4; j++) {
                float p = __expf(acc[i][j] * scale - mnew);
                Ps[(ty * 4 + i) * 64 + tx * 4 + j] = p;
                psum += p;
            }
#pragma unroll
            for (int o2 = 1; o2 < 16; o2 <<= 1)
                psum += __shfl_xor_sync(0xffffffffu, psum, o2);
            l_i[i] = l_i[i] * corr + psum;
            m_i[i] = mnew;
#pragma unroll
            for (int c = 0; c < 8; c++) oacc[i][c] *= corr;
        }
        __syncthreads();

        // O += P @ V  (O cols strided: c = tx + 16*cc -> conflict-free Vs reads)
#pragma unroll 2
        for (int j = 0; j < BK; j++) {
            float pr[4], vv[8];
#pragma unroll
            for (int i = 0; i < 4; i++) pr[i] = Ps[(ty * 4 + i) * 64 + j];
#pragma unroll
            for (int c = 0; c < 8; c++) vv[c] = Vs[j * DD + tx + 16 * c];
#pragma unroll
            for (int i = 0; i < 4; i++)
#pragma unroll
                for (int c = 0; c < 8; c++)
                    oacc[i][c] = fmaf(pr[i], vv[c], oacc[i][c]);
        }
    }

    // epilogue: normalize by l and store
#pragma unroll
    for (int i = 0; i < 4; i++) {
        int row = q0 + ty * 4 + i;
        float invl = 1.0f / l_i[i];
#pragma unroll
        for (int c = 0; c < 8; c++) {
            o[((size_t)row * HH + h) * DD + tx + 16 * c] = oacc[i][c] * invl;
        }
    }
}

// ---------------------------------------------------------------------------
extern "C" void kernel_launch(void* const* d_in, const int* in_sizes, int n_in,
                              void* d_out, int out_size)
{
    const float* x    = (const float*)d_in[0];
    const float* rope = (const float*)d_in[1];
    const float* Wq   = (const float*)d_in[2];
    const float* bq   = (const float*)d_in[3];
    const float* Wk   = (const float*)d_in[4];
    const float* bk   = (const float*)d_in[5];
    const float* Wv   = (const float*)d_in[6];
    const float* bv   = (const float*)d_in[7];
    const float* qn_w = (const float*)d_in[8];
    const float* kn_w = (const float*)d_in[9];
    const float* Wo   = (const float*)d_in[10];
    const float* bo   = (const float*)d_in[11];
    float* out = (float*)d_out;

    float *qp, *kp, *vp, *ap;
    cudaGetSymbolAddress((void**)&qp, g_q);
    cudaGetSymbolAddress((void**)&kp, g_k);
    cudaGetSymbolAddress((void**)&vp, g_v);
    cudaGetSymbolAddress((void**)&ap, g_attn);

    const int smem_attn = (3 * 64 * 128 + 64 * 64) * sizeof(float); // 114688
    cudaFuncSetAttribute(flash_attn, cudaFuncAttributeMaxDynamicSharedMemorySize,
                         smem_attn);

    dim3 ggrid(CC / 64, SS / 128);   // (N/64, M/128)
    gemm_nt_bias<<<ggrid, 256>>>(x, Wq, bq, qp, SS, CC, CC);
    gemm_nt_bias<<<ggrid, 256>>>(x, Wk, bk, kp, SS, CC, CC);
    gemm_nt_bias<<<ggrid, 256>>>(x, Wv, bv, vp, SS, CC, CC);

    dim3 ngrid(SS * HH, 2);
    norm_rope<<<ngrid, 128>>>(qp, kp, qn_w, kn_w, rope);

    dim3 agrid(SS / 64, HH);
    flash_attn<<<agrid, 256, smem_attn>>>(qp, kp, vp, ap);

    gemm_nt_bias<<<ggrid, 256>>>(ap, Wo, bo, out, SS, CC, CC);
}

// round 5
// speedup vs baseline: 3.0492x; 3.0492x over previous
#include <cuda_runtime.h>
#include <cstdint>
#include <mma.h>
#include <math.h>

using namespace nvcuda;

#define SS 4096
#define CC 2048
#define HH 16
#define DD 128
#define EPSF 1.1920929e-07f

// Scratch (no cudaMalloc allowed)
__device__ float g_q[SS * CC];
__device__ float g_k[SS * CC];
__device__ float g_v[SS * CC];
__device__ float g_attn[SS * CC];

// ---------------------------------------------------------------------------
// helpers
// ---------------------------------------------------------------------------
__device__ __forceinline__ uint32_t f2tf32(float x) {
    uint32_t r;
    asm("cvt.rna.tf32.f32 %0, %1;\n" : "=r"(r) : "f"(x));
    return r;
}

__device__ __forceinline__ void mma8(float* c, const uint32_t* a,
                                     uint32_t b0, uint32_t b1) {
    asm volatile(
        "mma.sync.aligned.m16n8k8.row.col.f32.tf32.tf32.f32 "
        "{%0,%1,%2,%3}, {%4,%5,%6,%7}, {%8,%9}, {%0,%1,%2,%3};\n"
        : "+f"(c[0]), "+f"(c[1]), "+f"(c[2]), "+f"(c[3])
        : "r"(a[0]), "r"(a[1]), "r"(a[2]), "r"(a[3]), "r"(b0), "r"(b1));
}

// ---------------------------------------------------------------------------
// GEMM: Out[M,N] = A[M,K] @ B[N,K]^T + bias[N]
// 3xTF32 (hi/lo split) wmma, 128x128x32 tile, 256 threads = 8 warps (2x4).
// hi/lo precomputed into smem at the load stage.
// ---------------------------------------------------------------------------
__global__ void __launch_bounds__(256)
gemm_nt_3xtf32(const float* __restrict__ A,
               const float* __restrict__ B,
               const float* __restrict__ bias,
               float* __restrict__ Out,
               int M, int N, int K)
{
    extern __shared__ float smem[];
    float* As_hi = smem;                  // [128][36]
    float* As_lo = smem + 128 * 36;
    float* Bs_hi = smem + 2 * 128 * 36;
    float* Bs_lo = smem + 3 * 128 * 36;

    const int t = threadIdx.x;
    const int warp = t >> 5;
    const int wr = warp >> 2;   // 0..1
    const int wc = warp & 3;    // 0..3
    const int m0 = blockIdx.y * 128;
    const int n0 = blockIdx.x * 128;

    wmma::fragment<wmma::accumulator, 16, 16, 8, float> cfrag[4][2];
#pragma unroll
    for (int mi = 0; mi < 4; mi++)
#pragma unroll
        for (int nj = 0; nj < 2; nj++) wmma::fill_fragment(cfrag[mi][nj], 0.0f);

    for (int k0 = 0; k0 < K; k0 += 32) {
#pragma unroll
        for (int i = 0; i < 4; i++) {
            int idx = i * 256 + t;            // 0..1023
            int r = idx >> 3, c4 = (idx & 7) * 4;
            float4 av = *(const float4*)&A[(size_t)(m0 + r) * K + k0 + c4];
            float4 bv = *(const float4*)&B[(size_t)(n0 + r) * K + k0 + c4];
            float4 ah, al, bh, bl;
            ah.x = __uint_as_float(f2tf32(av.x)); al.x = __uint_as_float(f2tf32(av.x - ah.x));
            ah.y = __uint_as_float(f2tf32(av.y)); al.y = __uint_as_float(f2tf32(av.y - ah.y));
            ah.z = __uint_as_float(f2tf32(av.z)); al.z = __uint_as_float(f2tf32(av.z - ah.z));
            ah.w = __uint_as_float(f2tf32(av.w)); al.w = __uint_as_float(f2tf32(av.w - ah.w));
            bh.x = __uint_as_float(f2tf32(bv.x)); bl.x = __uint_as_float(f2tf32(bv.x - bh.x));
            bh.y = __uint_as_float(f2tf32(bv.y)); bl.y = __uint_as_float(f2tf32(bv.y - bh.y));
            bh.z = __uint_as_float(f2tf32(bv.z)); bl.z = __uint_as_float(f2tf32(bv.z - bh.z));
            bh.w = __uint_as_float(f2tf32(bv.w)); bl.w = __uint_as_float(f2tf32(bv.w - bh.w));
            *(float4*)&As_hi[r * 36 + c4] = ah;
            *(float4*)&As_lo[r * 36 + c4] = al;
            *(float4*)&Bs_hi[r * 36 + c4] = bh;
            *(float4*)&Bs_lo[r * 36 + c4] = bl;
        }
        __syncthreads();

#pragma unroll
        for (int ks = 0; ks < 4; ks++) {
            wmma::fragment<wmma::matrix_a, 16, 16, 8, wmma::precision::tf32,
                           wmma::row_major> ah[4], al[4];
            wmma::fragment<wmma::matrix_b, 16, 16, 8, wmma::precision::tf32,
                           wmma::col_major> bh[2], bl[2];
#pragma unroll
            for (int mi = 0; mi < 4; mi++) {
                wmma::load_matrix_sync(ah[mi], &As_hi[(wr * 64 + mi * 16) * 36 + ks * 8], 36);
                wmma::load_matrix_sync(al[mi], &As_lo[(wr * 64 + mi * 16) * 36 + ks * 8], 36);
            }
#pragma unroll
            for (int nj = 0; nj < 2; nj++) {
                wmma::load_matrix_sync(bh[nj], &Bs_hi[(wc * 32 + nj * 16) * 36 + ks * 8], 36);
                wmma::load_matrix_sync(bl[nj], &Bs_lo[(wc * 32 + nj * 16) * 36 + ks * 8], 36);
            }
            // lo*hi + hi*lo first, hi*hi last
#pragma unroll
            for (int mi = 0; mi < 4; mi++)
#pragma unroll
                for (int nj = 0; nj < 2; nj++) {
                    wmma::mma_sync(cfrag[mi][nj], al[mi], bh[nj], cfrag[mi][nj]);
                    wmma::mma_sync(cfrag[mi][nj], ah[mi], bl[nj], cfrag[mi][nj]);
                    wmma::mma_sync(cfrag[mi][nj], ah[mi], bh[nj], cfrag[mi][nj]);
                }
        }
        __syncthreads();
    }

    // epilogue: stage to smem (aliases tiles; all warps synced), add bias
    float* Cs = smem;  // [128][132] = 67584 B <= 73728 B
#pragma unroll
    for (int mi = 0; mi < 4; mi++)
#pragma unroll
        for (int nj = 0; nj < 2; nj++)
            wmma::store_matrix_sync(&Cs[(wr * 64 + mi * 16) * 132 + wc * 32 + nj * 16],
                                    cfrag[mi][nj], 132, wmma::mem_row_major);
    __syncthreads();

#pragma unroll
    for (int i = 0; i < 16; i++) {
        int idx = i * 256 + t;               // 0..4095
        int r = idx >> 5, c4 = (idx & 31) * 4;
        float4 cv = *(float4*)&Cs[r * 132 + c4];
        float4 bb = *(const float4*)&bias[n0 + c4];
        cv.x += bb.x; cv.y += bb.y; cv.z += bb.z; cv.w += bb.w;
        *(float4*)&Out[(size_t)(m0 + r) * N + n0 + c4] = cv;
    }
}

// ---------------------------------------------------------------------------
// Fused per-head RMSNorm + rotary
// ---------------------------------------------------------------------------
__global__ void norm_rope(float* __restrict__ q, float* __restrict__ k,
                          const float* __restrict__ qw,
                          const float* __restrict__ kw,
                          const float* __restrict__ rope)
{
    const int sh = blockIdx.x;
    const int s  = sh >> 4;
    float* x       = (blockIdx.y == 0) ? q  : k;
    const float* w = (blockIdx.y == 0) ? qw : kw;

    const int d = threadIdx.x;
    float v = x[(size_t)sh * DD + d];

    float ss = v * v;
#pragma unroll
    for (int o = 16; o > 0; o >>= 1) ss += __shfl_xor_sync(0xffffffffu, ss, o);
    __shared__ float wsum[4];
    __shared__ float nrm[DD];
    if ((d & 31) == 0) wsum[d >> 5] = ss;
    __syncthreads();
    float tot = wsum[0] + wsum[1] + wsum[2] + wsum[3];
    float inv = rsqrtf(tot * (1.0f / DD) + EPSF);
    nrm[d] = v * inv * w[d];
    __syncthreads();

    int p = d >> 1, i = d & 1;
    const float* r = rope + (size_t)s * 256 + p * 4 + i * 2;
    float out = r[0] * nrm[2 * p] + r[1] * nrm[2 * p + 1];
    x[(size_t)sh * DD + d] = out;
}

// ---------------------------------------------------------------------------
// Flash attention, online softmax in registers.
// QK^T in 3xTF32 (Q hi in regs, Q lo / K hi / K lo in smem); PV in 1xTF32.
// Block: (128-query tile, head). 256 threads = 8 warps; warp owns 16 q rows.
// smem (tf32 bit words): Qlo[128][132] Ks_hi[64][132] Ks_lo[64][132]
//                        Vs[64][136] Ps[128][68]  -> 204800 B
// ---------------------------------------------------------------------------
__global__ void __launch_bounds__(256, 1)
flash_attn_tc(const float* __restrict__ q,
              const float* __restrict__ k,
              const float* __restrict__ v,
              float* __restrict__ o)
{
    extern __shared__ uint32_t usm[];
    uint32_t* Qlo  = usm;                    // [128][132]
    uint32_t* Ks_hi = Qlo + 128 * 132;       // [64][132]
    uint32_t* Ks_lo = Ks_hi + 64 * 132;      // [64][132]
    uint32_t* Vs    = Ks_lo + 64 * 132;      // [64][136]
    uint32_t* Ps    = Vs + 64 * 136;         // [128][68]

    const int h  = blockIdx.y;
    const int q0 = blockIdx.x * 128;
    const int t  = threadIdx.x;
    const int warp = t >> 5;
    const int lane = t & 31;
    const int g   = lane >> 2;   // 0..7
    const int tig = lane & 3;    // 0..3
    const int r0 = warp * 16 + g;      // local row (group 0), 0..127
    const int r1 = r0 + 8;             // local row (group 1)
    const float scale = 0.08838834764831845f;  // 1/sqrt(128)

    // Q -> hi in registers, lo in smem (thread-private addressing)
    uint32_t qhi[16][4];
    {
        const float* qr0 = &q[((size_t)(q0 + r0) * HH + h) * DD];
        const float* qr1 = &q[((size_t)(q0 + r1) * HH + h) * DD];
#pragma unroll
        for (int ks = 0; ks < 16; ks++) {
            int c = ks * 8 + tig;
            float q00 = qr0[c] * scale;
            float q10 = qr1[c] * scale;
            float q01 = qr0[c + 4] * scale;
            float q11 = qr1[c + 4] * scale;
            qhi[ks][0] = f2tf32(q00);
            qhi[ks][1] = f2tf32(q10);
            qhi[ks][2] = f2tf32(q01);
            qhi[ks][3] = f2tf32(q11);
            Qlo[r0 * 132 + c]     = f2tf32(q00 - __uint_as_float(qhi[ks][0]));
            Qlo[r1 * 132 + c]     = f2tf32(q10 - __uint_as_float(qhi[ks][1]));
            Qlo[r0 * 132 + c + 4] = f2tf32(q01 - __uint_as_float(qhi[ks][2]));
            Qlo[r1 * 132 + c + 4] = f2tf32(q11 - __uint_as_float(qhi[ks][3]));
        }
    }

    float m0r = -1e30f, m1r = -1e30f, l0 = 0.0f, l1 = 0.0f;
    float oacc[16][4];
#pragma unroll
    for (int j = 0; j < 16; j++)
#pragma unroll
        for (int e = 0; e < 4; e++) oacc[j][e] = 0.0f;

    for (int kv0 = 0; kv0 < SS; kv0 += 64) {
        __syncthreads();   // all warps done reading Ks/Vs from prev iter
        // fill K (hi/lo) and V (tf32) tiles: 64x128, 2048 float4 / 256 thr
#pragma unroll
        for (int i = 0; i < 8; i++) {
            int idx = i * 256 + t;
            int r = idx >> 5, c4 = (idx & 31) * 4;
            size_t goff = ((size_t)(kv0 + r) * HH + h) * DD + c4;
            float4 kv4 = *(const float4*)&k[goff];
            float4 vv4 = *(const float4*)&v[goff];
            uint4 kh, kl;
            kh.x = f2tf32(kv4.x); kl.x = f2tf32(kv4.x - __uint_as_float(kh.x));
            kh.y = f2tf32(kv4.y); kl.y = f2tf32(kv4.y - __uint_as_float(kh.y));
            kh.z = f2tf32(kv4.z); kl.z = f2tf32(kv4.z - __uint_as_float(kh.z));
            kh.w = f2tf32(kv4.w); kl.w = f2tf32(kv4.w - __uint_as_float(kh.w));
            uint4 vu = make_uint4(f2tf32(vv4.x), f2tf32(vv4.y),
                                  f2tf32(vv4.z), f2tf32(vv4.w));
            *(uint4*)&Ks_hi[r * 132 + c4] = kh;
            *(uint4*)&Ks_lo[r * 132 + c4] = kl;
            *(uint4*)&Vs[r * 136 + c4]    = vu;
        }
        __syncthreads();

        // scores: 16x64 per warp = 8 n-frags, k = 128 (16 ksteps), 3xTF32
        float sacc[8][4];
#pragma unroll
        for (int j = 0; j < 8; j++)
#pragma unroll
            for (int e = 0; e < 4; e++) sacc[j][e] = 0.0f;

#pragma unroll
        for (int ks = 0; ks < 16; ks++) {
            uint32_t aql[4];
            aql[0] = Qlo[r0 * 132 + ks * 8 + tig];
            aql[1] = Qlo[r1 * 132 + ks * 8 + tig];
            aql[2] = Qlo[r0 * 132 + ks * 8 + tig + 4];
            aql[3] = Qlo[r1 * 132 + ks * 8 + tig + 4];
#pragma unroll
            for (int j = 0; j < 8; j++) {
                uint32_t bh0 = Ks_hi[(j * 8 + g) * 132 + ks * 8 + tig];
                uint32_t bh1 = Ks_hi[(j * 8 + g) * 132 + ks * 8 + tig + 4];
                uint32_t bl0 = Ks_lo[(j * 8 + g) * 132 + ks * 8 + tig];
                uint32_t bl1 = Ks_lo[(j * 8 + g) * 132 + ks * 8 + tig + 4];
                mma8(sacc[j], aql,     bh0, bh1);   // lo*hi
                mma8(sacc[j], qhi[ks], bl0, bl1);   // hi*lo
                mma8(sacc[j], qhi[ks], bh0, bh1);   // hi*hi
            }
        }

        // online softmax (rows r0 and r1; quad = 4 lanes per row)
        float rmax0 = -1e30f, rmax1 = -1e30f;
#pragma unroll
        for (int j = 0; j < 8; j++) {
            rmax0 = fmaxf(rmax0, fmaxf(sacc[j][0], sacc[j][1]));
            rmax1 = fmaxf(rmax1, fmaxf(sacc[j][2], sacc[j][3]));
        }
#pragma unroll
        for (int off = 1; off < 4; off <<= 1) {
            rmax0 = fmaxf(rmax0, __shfl_xor_sync(0xffffffffu, rmax0, off));
            rmax1 = fmaxf(rmax1, __shfl_xor_sync(0xffffffffu, rmax1, off));
        }
        float mn0 = fmaxf(m0r, rmax0);
        float mn1 = fmaxf(m1r, rmax1);
        float cr0 = __expf(m0r - mn0);
        float cr1 = __expf(m1r - mn1);
        float rs0 = 0.0f, rs1 = 0.0f;
#pragma unroll
        for (int j = 0; j < 8; j++) {
            float e0 = __expf(sacc[j][0] - mn0);
            float e1 = __expf(sacc[j][1] - mn0);
            float e2 = __expf(sacc[j][2] - mn1);
            float e3 = __expf(sacc[j][3] - mn1);
            rs0 += e0 + e1;
            rs1 += e2 + e3;
            int col = j * 8 + 2 * tig;
            Ps[r0 * 68 + col]     = f2tf32(e0);
            Ps[r0 * 68 + col + 1] = f2tf32(e1);
            Ps[r1 * 68 + col]     = f2tf32(e2);
            Ps[r1 * 68 + col + 1] = f2tf32(e3);
        }
#pragma unroll
        for (int off = 1; off < 4; off <<= 1) {
            rs0 += __shfl_xor_sync(0xffffffffu, rs0, off);
            rs1 += __shfl_xor_sync(0xffffffffu, rs1, off);
        }
        l0 = l0 * cr0 + rs0;
        l1 = l1 * cr1 + rs1;
        m0r = mn0;
        m1r = mn1;
#pragma unroll
        for (int j = 0; j < 16; j++) {
            oacc[j][0] *= cr0; oacc[j][1] *= cr0;
            oacc[j][2] *= cr1; oacc[j][3] *= cr1;
        }
        __syncwarp();

        // O += P @ V : k = 64 (8 ksteps), n = 128 (16 frags), 1xTF32
#pragma unroll
        for (int kc = 0; kc < 8; kc++) {
            uint32_t a[4];
            a[0] = Ps[r0 * 68 + kc * 8 + tig];
            a[1] = Ps[r1 * 68 + kc * 8 + tig];
            a[2] = Ps[r0 * 68 + kc * 8 + tig + 4];
            a[3] = Ps[r1 * 68 + kc * 8 + tig + 4];
#pragma unroll
            for (int j = 0; j < 16; j++) {
                uint32_t b0 = Vs[(kc * 8 + tig) * 136 + j * 8 + g];
                uint32_t b1 = Vs[(kc * 8 + tig + 4) * 136 + j * 8 + g];
                mma8(oacc[j], a, b0, b1);
            }
        }
    }

    // epilogue
    float inv0 = 1.0f / l0, inv1 = 1.0f / l1;
    float* o0 = &o[((size_t)(q0 + r0) * HH + h) * DD];
    float* o1 = &o[((size_t)(q0 + r1) * HH + h) * DD];
#pragma unroll
    for (int j = 0; j < 16; j++) {
        int col = j * 8 + 2 * tig;
        float2 s0 = make_float2(oacc[j][0] * inv0, oacc[j][1] * inv0);
        float2 s1 = make_float2(oacc[j][2] * inv1, oacc[j][3] * inv1);
        *(float2*)&o0[col] = s0;
        *(float2*)&o1[col] = s1;
    }
}

// ---------------------------------------------------------------------------
extern "C" void kernel_launch(void* const* d_in, const int* in_sizes, int n_in,
                              void* d_out, int out_size)
{
    const float* x    = (const float*)d_in[0];
    const float* rope = (const float*)d_in[1];
    const float* Wq   = (const float*)d_in[2];
    const float* bq   = (const float*)d_in[3];
    const float* Wk   = (const float*)d_in[4];
    const float* bk   = (const float*)d_in[5];
    const float* Wv   = (const float*)d_in[6];
    const float* bv   = (const float*)d_in[7];
    const float* qn_w = (const float*)d_in[8];
    const float* kn_w = (const float*)d_in[9];
    const float* Wo   = (const float*)d_in[10];
    const float* bo   = (const float*)d_in[11];
    float* out = (float*)d_out;

    float *qp, *kp, *vp, *ap;
    cudaGetSymbolAddress((void**)&qp, g_q);
    cudaGetSymbolAddress((void**)&kp, g_k);
    cudaGetSymbolAddress((void**)&vp, g_v);
    cudaGetSymbolAddress((void**)&ap, g_attn);

    const int smem_gemm = 4 * 128 * 36 * sizeof(float);              // 73728
    const int smem_attn = (128 * 132 + 2 * 64 * 132 + 64 * 136 + 128 * 68) * 4; // 204800
    cudaFuncSetAttribute(gemm_nt_3xtf32, cudaFuncAttributeMaxDynamicSharedMemorySize,
                         smem_gemm);
    cudaFuncSetAttribute(flash_attn_tc, cudaFuncAttributeMaxDynamicSharedMemorySize,
                         smem_attn);

    dim3 ggrid(CC / 128, SS / 128);
    gemm_nt_3xtf32<<<ggrid, 256, smem_gemm>>>(x, Wq, bq, qp, SS, CC, CC);
    gemm_nt_3xtf32<<<ggrid, 256, smem_gemm>>>(x, Wk, bk, kp, SS, CC, CC);
    gemm_nt_3xtf32<<<ggrid, 256, smem_gemm>>>(x, Wv, bv, vp, SS, CC, CC);

    dim3 ngrid(SS * HH, 2);
    norm_rope<<<ngrid, 128>>>(qp, kp, qn_w, kn_w, rope);

    dim3 agrid(SS / 128, HH);
    flash_attn_tc<<<agrid, 256, smem_attn>>>(qp, kp, vp, ap);

    gemm_nt_3xtf32<<<ggrid, 256, smem_gemm>>>(ap, Wo, bo, out, SS, CC, CC);
}